// round 6
// baseline (speedup 1.0000x reference)
#include <cuda_runtime.h>
#include <cstdint>

// y2[a,d,z] = sum_c ( sum_b x1[a,b,z]*x0[b,c,z] ) * x2[c,d,z]
// All tensors (32,32,32768) fp32 row-major, z contiguous. Lane = f32x2 z-pair.
// Fused two-pass; y1 in 64KB smem. 4-stage cp.async pipeline stages the
// DRAM-latency stream (x0 in pass1, x2 in pass2) into 8KB smem slots.
// Warp tile 8a x 4c; av (x1) via register-prefetched LDG (L1-shared across warps).
// Block: 256 thr, 8 warps, 8 a-rows x 32 z-pairs. 96KB smem -> 2 blocks/SM.

#define ZH   16384
#define SDIM 32

using u64 = unsigned long long;

__device__ __forceinline__ u64 ffma2(u64 a, u64 b, u64 c) {
    u64 d;
    asm("fma.rn.f32x2 %0, %1, %2, %3;" : "=l"(d) : "l"(a), "l"(b), "l"(c));
    return d;
}

__device__ __forceinline__ void cp16(u64* dst, const u64* src) {
    unsigned d = (unsigned)__cvta_generic_to_shared(dst);
    asm volatile("cp.async.cg.shared.global [%0], [%1], 16;"
                 :: "r"(d), "l"(src) : "memory");
}
__device__ __forceinline__ void cp_commit() {
    asm volatile("cp.async.commit_group;" ::: "memory");
}
__device__ __forceinline__ void cp_wait2() {
    asm volatile("cp.async.wait_group 2;" ::: "memory");
}

// Fill one stage slot: 32 rows x 32 z-pairs (8KB). base = tensor + rowgroup*32*ZH + zb.
// 512 16-byte chunks, 2 per thread.
__device__ __forceinline__ void fill_stage(u64* slot, const u64* base, int tid) {
    #pragma unroll
    for (int h = 0; h < 2; h++) {
        int q = tid + h * 256;
        int r = q >> 4;          // row 0..31
        int m = q & 15;          // 16B chunk within row
        cp16(slot + r * 32 + 2 * m, base + (size_t)r * ZH + 2 * m);
    }
}

__global__ void __launch_bounds__(256)
einnet_pipe_kernel(const u64* __restrict__ x0,
                   const u64* __restrict__ x1,
                   const u64* __restrict__ x2,
                   u64* __restrict__ out)
{
    extern __shared__ u64 smem[];
    u64* stg = smem;            // 4 stages x 1024 u64 = 32KB
    u64* y1s = smem + 4096;     // 8192 u64 = 64KB

    const int tid  = threadIdx.x;
    const int lane = tid & 31;
    const int w    = tid >> 5;
    const int abas = blockIdx.x * 8;
    const int zb   = blockIdx.y * 32;
    const int p    = zb + lane;
    const int c0   = w * 4;

    // ================= Pass 1: y1[a,c] = sum_b x1[a,b] * x0[b,c] =================
    const u64* __restrict__ Ap = x1 + (size_t)(abas * SDIM) * ZH + p;
    const u64* __restrict__ B0 = x0 + zb;

    #pragma unroll
    for (int k = 0; k < 3; k++) {
        fill_stage(stg + k * 1024, B0 + (size_t)(k * SDIM) * ZH, tid);
        cp_commit();
    }

    u64 acc[8][4];
    #pragma unroll
    for (int i = 0; i < 8; i++)
        #pragma unroll
        for (int j = 0; j < 4; j++) acc[i][j] = 0ull;

    u64 av[8];
    #pragma unroll
    for (int i = 0; i < 8; i++) av[i] = Ap[(size_t)(i * SDIM) * ZH];

    for (int b = 0; b < SDIM; b++) {
        cp_wait2();                 // slot b%4 data complete (this thread's view)
        __syncthreads();            // all threads waited -> data visible; prev slot free
        if (b + 3 < SDIM)
            fill_stage(stg + ((b + 3) & 3) * 1024,
                       B0 + (size_t)((b + 3) * SDIM) * ZH, tid);
        cp_commit();                // unconditional: keeps group counting uniform

        // register-prefetch av for next step
        u64 avn[8];
        const int bn = (b + 1 < SDIM) ? b + 1 : b;
        #pragma unroll
        for (int i = 0; i < 8; i++) avn[i] = Ap[(size_t)(i * SDIM + bn) * ZH];

        const u64* __restrict__ slot = stg + (b & 3) * 1024;
        u64 bv[4];
        #pragma unroll
        for (int j = 0; j < 4; j++) bv[j] = slot[(c0 + j) * 32 + lane];

        #pragma unroll
        for (int i = 0; i < 8; i++)
            #pragma unroll
            for (int j = 0; j < 4; j++)
                acc[i][j] = ffma2(av[i], bv[j], acc[i][j]);

        #pragma unroll
        for (int i = 0; i < 8; i++) av[i] = avn[i];
    }

    // store y1 stripe (conflict-free lane-consecutive 8B)
    #pragma unroll
    for (int i = 0; i < 8; i++)
        #pragma unroll
        for (int j = 0; j < 4; j++)
            y1s[(i * SDIM + c0 + j) * 32 + lane] = acc[i][j];
    __syncthreads();   // y1 visible; all pass-1 slot reads finished

    // ================= Pass 2: y2[a,d] = sum_c y1[a,c] * x2[c,d] =================
    const u64* __restrict__ C0 = x2 + zb;

    #pragma unroll
    for (int k = 0; k < 3; k++) {
        fill_stage(stg + k * 1024, C0 + (size_t)(k * SDIM) * ZH, tid);
        cp_commit();
    }

    #pragma unroll
    for (int i = 0; i < 8; i++)
        #pragma unroll
        for (int j = 0; j < 4; j++) acc[i][j] = 0ull;

    for (int c = 0; c < SDIM; c++) {
        cp_wait2();
        __syncthreads();
        if (c + 3 < SDIM)
            fill_stage(stg + ((c + 3) & 3) * 1024,
                       C0 + (size_t)((c + 3) * SDIM) * ZH, tid);
        cp_commit();

        const u64* __restrict__ slot = stg + (c & 3) * 1024;
        u64 xv[4];
        #pragma unroll
        for (int j = 0; j < 4; j++) xv[j] = slot[(c0 + j) * 32 + lane];
        u64 yv[8];
        #pragma unroll
        for (int i = 0; i < 8; i++) yv[i] = y1s[(i * SDIM + c) * 32 + lane];

        #pragma unroll
        for (int i = 0; i < 8; i++)
            #pragma unroll
            for (int j = 0; j < 4; j++)
                acc[i][j] = ffma2(yv[i], xv[j], acc[i][j]);
    }

    u64* __restrict__ Op = out + (size_t)(abas * SDIM + c0) * ZH + p;
    #pragma unroll
    for (int i = 0; i < 8; i++)
        #pragma unroll
        for (int j = 0; j < 4; j++)
            Op[(size_t)(i * SDIM + j) * ZH] = acc[i][j];
}

extern "C" void kernel_launch(void* const* d_in, const int* in_sizes, int n_in,
                              void* d_out, int out_size)
{
    (void)in_sizes; (void)n_in; (void)out_size;
    const u64* x0 = (const u64*)d_in[0];   // (b, c, Z)
    const u64* x1 = (const u64*)d_in[1];   // (a, b, Z)
    const u64* x2 = (const u64*)d_in[2];   // (c, d, Z)
    u64* out = (u64*)d_out;

    constexpr int SMEM_BYTES = (4096 + 8192) * 8;   // 98304 = 96KB
    cudaFuncSetAttribute(einnet_pipe_kernel,
                         cudaFuncAttributeMaxDynamicSharedMemorySize, SMEM_BYTES);

    // z-tile slow dim: the 4 a-group blocks of one z-tile are co-resident and
    // share x0/x2 slices in L2.
    dim3 grid(4, ZH / 32);
    einnet_pipe_kernel<<<grid, 256, SMEM_BYTES>>>(x0, x1, x2, out);
}

// round 7
// speedup vs baseline: 1.0703x; 1.0703x over previous
#include <cuda_runtime.h>
#include <cstdint>

// y2[a,d,z] = sum_c ( sum_b x1[a,b,z]*x0[b,c,z] ) * x2[c,d,z]
// All tensors (32,32,32768) fp32 row-major, z contiguous. Lane = one f32x2 z-pair.
// Fused two-pass, y1 in 64KB smem, no in-loop barriers (R4 structure).
// New in R7: explicit distance-2 register prefetch (3-name rotation) for the
// DRAM-latency stream (x0 in pass 1, x2 in pass 2) to cover ~940cyc miss latency.
// Warp tile 8a x 4c = 32 u64 acc. Block: 256 thr, 8 a-rows x 32 z-pairs. 2 blocks/SM.

#define ZH   16384          // z-pairs (f32x2)
#define SDIM 32

using u64 = unsigned long long;

__device__ __forceinline__ u64 ffma2(u64 a, u64 b, u64 c) {
    u64 d;
    asm("fma.rn.f32x2 %0, %1, %2, %3;" : "=l"(d) : "l"(a), "l"(b), "l"(c));
    return d;
}

__global__ void __launch_bounds__(256, 2)
einnet_fused4_kernel(const u64* __restrict__ x0,
                     const u64* __restrict__ x1,
                     const u64* __restrict__ x2,
                     u64* __restrict__ out)
{
    // y1 tile: [a(8)][c(32)][lane(32)] u64 = 64KB
    extern __shared__ u64 y1s[];

    const int lane = threadIdx.x & 31;
    const int w    = threadIdx.x >> 5;            // 0..7
    const int abas = blockIdx.x * 8;              // a-group base
    const int p    = blockIdx.y * 32 + lane;      // global z-pair
    const int c0   = w * 4;                       // this warp's c/d stripe

    u64 acc[8][4];
    #pragma unroll
    for (int i = 0; i < 8; i++)
        #pragma unroll
        for (int j = 0; j < 4; j++) acc[i][j] = 0ull;

    // ---------------- Pass 1: y1[a,c] = sum_b x1[a,b] * x0[b,c] ----------------
    const u64* __restrict__ Ap = x1 + (size_t)(abas * SDIM) * ZH + p;
    const u64* __restrict__ Bp = x0 + (size_t)c0 * ZH + p;

    u64 bv_c[4], bv_n[4];
    #pragma unroll
    for (int j = 0; j < 4; j++) {
        bv_c[j] = Bp[(size_t)(0 * SDIM + j) * ZH];
        bv_n[j] = Bp[(size_t)(1 * SDIM + j) * ZH];
    }

    #pragma unroll 2
    for (int b = 0; b < SDIM; b++) {
        // distance-2 prefetch of the DRAM stream (clamped at tail; dup loads are L1 hits)
        const int bf = (b + 2 < SDIM) ? b + 2 : SDIM - 1;
        u64 bv_f[4];
        #pragma unroll
        for (int j = 0; j < 4; j++) bv_f[j] = Bp[(size_t)(bf * SDIM + j) * ZH];

        u64 av[8];
        #pragma unroll
        for (int i = 0; i < 8; i++) av[i] = Ap[(size_t)(i * SDIM + b) * ZH];

        #pragma unroll
        for (int i = 0; i < 8; i++)
            #pragma unroll
            for (int j = 0; j < 4; j++)
                acc[i][j] = ffma2(av[i], bv_c[j], acc[i][j]);

        #pragma unroll
        for (int j = 0; j < 4; j++) { bv_c[j] = bv_n[j]; bv_n[j] = bv_f[j]; }
    }

    // store y1 stripe (conflict-free: lane-consecutive 8B)
    #pragma unroll
    for (int i = 0; i < 8; i++)
        #pragma unroll
        for (int j = 0; j < 4; j++)
            y1s[(i * SDIM + c0 + j) * 32 + lane] = acc[i][j];
    __syncthreads();

    // ---------------- Pass 2: y2[a,d] = sum_c y1[a,c] * x2[c,d] ----------------
    #pragma unroll
    for (int i = 0; i < 8; i++)
        #pragma unroll
        for (int j = 0; j < 4; j++) acc[i][j] = 0ull;

    const u64* __restrict__ Cp = x2 + (size_t)c0 * ZH + p;

    u64 xv_c[4], xv_n[4];
    #pragma unroll
    for (int j = 0; j < 4; j++) {
        xv_c[j] = Cp[(size_t)(0 * SDIM + j) * ZH];
        xv_n[j] = Cp[(size_t)(1 * SDIM + j) * ZH];
    }

    #pragma unroll 2
    for (int c = 0; c < SDIM; c++) {
        const int cf = (c + 2 < SDIM) ? c + 2 : SDIM - 1;
        u64 xv_f[4];
        #pragma unroll
        for (int j = 0; j < 4; j++) xv_f[j] = Cp[(size_t)(cf * SDIM + j) * ZH];

        u64 yv[8];
        #pragma unroll
        for (int i = 0; i < 8; i++) yv[i] = y1s[(i * SDIM + c) * 32 + lane];

        #pragma unroll
        for (int i = 0; i < 8; i++)
            #pragma unroll
            for (int j = 0; j < 4; j++)
                acc[i][j] = ffma2(yv[i], xv_c[j], acc[i][j]);

        #pragma unroll
        for (int j = 0; j < 4; j++) { xv_c[j] = xv_n[j]; xv_n[j] = xv_f[j]; }
    }

    u64* __restrict__ Op = out + (size_t)(abas * SDIM + c0) * ZH + p;
    #pragma unroll
    for (int i = 0; i < 8; i++)
        #pragma unroll
        for (int j = 0; j < 4; j++)
            Op[(size_t)(i * SDIM + j) * ZH] = acc[i][j];
}

extern "C" void kernel_launch(void* const* d_in, const int* in_sizes, int n_in,
                              void* d_out, int out_size)
{
    (void)in_sizes; (void)n_in; (void)out_size;
    const u64* x0 = (const u64*)d_in[0];   // (b, c, Z)
    const u64* x1 = (const u64*)d_in[1];   // (a, b, Z)
    const u64* x2 = (const u64*)d_in[2];   // (c, d, Z)
    u64* out = (u64*)d_out;

    constexpr int SMEM_BYTES = 8 * SDIM * 32 * 8;   // 65536
    cudaFuncSetAttribute(einnet_fused4_kernel,
                         cudaFuncAttributeMaxDynamicSharedMemorySize, SMEM_BYTES);

    // z-tile slow dim: the 4 a-group blocks of one z-tile are co-resident and
    // share x0/x2 slices in L2.
    dim3 grid(4, ZH / 32);
    einnet_fused4_kernel<<<grid, 256, SMEM_BYTES>>>(x0, x1, x2, out);
}

// round 9
// speedup vs baseline: 1.6313x; 1.5241x over previous
#include <cuda_runtime.h>
#include <cstdint>

// y2[a,d,z] = sum_c ( sum_b x1[a,b,z]*x0[b,c,z] ) * x2[c,d,z]
// All tensors (32,32,32768) fp32 row-major, z contiguous. Lane = one f32x2 z-pair.
// R4 structure (best so far): fused two-pass, y1 in 64KB smem, no in-loop
// barriers, warp tile 8a x 4c, 2 blocks/SM.
// R8 change: FULL unroll + compile-time double-buffered prefetch of the
// DRAM/L2 stream (bv in pass 1, xv in pass 2). Buffer index b&1 and the
// tail guard are resolved at compile time -> zero rotation MOVs, zero
// dynamic address ALU (the R7/R6 failure modes). av/yv stay load-at-use
// (L1/smem hits, already covered by the FFMA2 block).

#define ZH   16384          // z-pairs (f32x2)
#define SDIM 32

using u64 = unsigned long long;

__device__ __forceinline__ u64 ffma2(u64 a, u64 b, u64 c) {
    u64 d;
    asm("fma.rn.f32x2 %0, %1, %2, %3;" : "=l"(d) : "l"(a), "l"(b), "l"(c));
    return d;
}

__global__ void __launch_bounds__(256, 2)
einnet_fused5_kernel(const u64* __restrict__ x0,
                     const u64* __restrict__ x1,
                     const u64* __restrict__ x2,
                     u64* __restrict__ out)
{
    // y1 tile: [a(8)][c(32)][lane(32)] u64 = 64KB
    extern __shared__ u64 y1s[];

    const int lane = threadIdx.x & 31;
    const int w    = threadIdx.x >> 5;            // 0..7
    const int abas = blockIdx.x * 8;              // a-group base
    const int p    = blockIdx.y * 32 + lane;      // global z-pair
    const int c0   = w * 4;                       // this warp's c/d stripe

    u64 acc[8][4];
    #pragma unroll
    for (int i = 0; i < 8; i++)
        #pragma unroll
        for (int j = 0; j < 4; j++) acc[i][j] = 0ull;

    // ---------------- Pass 1: y1[a,c] = sum_b x1[a,b] * x0[b,c] ----------------
    const u64* __restrict__ Ap = x1 + (size_t)(abas * SDIM) * ZH + p;
    const u64* __restrict__ Bp = x0 + (size_t)c0 * ZH + p;

    u64 bv[2][4];
    #pragma unroll
    for (int j = 0; j < 4; j++) bv[0][j] = Bp[(size_t)j * ZH];

    #pragma unroll
    for (int b = 0; b < SDIM; b++) {
        const int cur = b & 1;           // compile-time after full unroll
        if (b + 1 < SDIM) {              // compile-time guard
            #pragma unroll
            for (int j = 0; j < 4; j++)
                bv[cur ^ 1][j] = Bp[(size_t)((b + 1) * SDIM + j) * ZH];
        }

        u64 av[8];
        #pragma unroll
        for (int i = 0; i < 8; i++) av[i] = Ap[(size_t)(i * SDIM + b) * ZH];

        #pragma unroll
        for (int i = 0; i < 8; i++)
            #pragma unroll
            for (int j = 0; j < 4; j++)
                acc[i][j] = ffma2(av[i], bv[cur][j], acc[i][j]);
    }

    // store y1 stripe (conflict-free: lane-consecutive 8B)
    #pragma unroll
    for (int i = 0; i < 8; i++)
        #pragma unroll
        for (int j = 0; j < 4; j++)
            y1s[(i * SDIM + c0 + j) * 32 + lane] = acc[i][j];
    __syncthreads();

    // ---------------- Pass 2: y2[a,d] = sum_c y1[a,c] * x2[c,d] ----------------
    #pragma unroll
    for (int i = 0; i < 8; i++)
        #pragma unroll
        for (int j = 0; j < 4; j++) acc[i][j] = 0ull;

    const u64* __restrict__ Cp = x2 + (size_t)c0 * ZH + p;

    u64 xv[2][4];
    #pragma unroll
    for (int j = 0; j < 4; j++) xv[0][j] = Cp[(size_t)j * ZH];

    #pragma unroll
    for (int c = 0; c < SDIM; c++) {
        const int cur = c & 1;
        if (c + 1 < SDIM) {
            #pragma unroll
            for (int j = 0; j < 4; j++)
                xv[cur ^ 1][j] = Cp[(size_t)((c + 1) * SDIM + j) * ZH];
        }

        u64 yv[8];
        #pragma unroll
        for (int i = 0; i < 8; i++) yv[i] = y1s[(i * SDIM + c) * 32 + lane];

        #pragma unroll
        for (int i = 0; i < 8; i++)
            #pragma unroll
            for (int j = 0; j < 4; j++)
                acc[i][j] = ffma2(yv[i], xv[cur][j], acc[i][j]);
    }

    u64* __restrict__ Op = out + (size_t)(abas * SDIM + c0) * ZH + p;
    #pragma unroll
    for (int i = 0; i < 8; i++)
        #pragma unroll
        for (int j = 0; j < 4; j++)
            Op[(size_t)(i * SDIM + j) * ZH] = acc[i][j];
}

extern "C" void kernel_launch(void* const* d_in, const int* in_sizes, int n_in,
                              void* d_out, int out_size)
{
    (void)in_sizes; (void)n_in; (void)out_size;
    const u64* x0 = (const u64*)d_in[0];   // (b, c, Z)
    const u64* x1 = (const u64*)d_in[1];   // (a, b, Z)
    const u64* x2 = (const u64*)d_in[2];   // (c, d, Z)
    u64* out = (u64*)d_out;

    constexpr int SMEM_BYTES = 8 * SDIM * 32 * 8;   // 65536
    cudaFuncSetAttribute(einnet_fused5_kernel,
                         cudaFuncAttributeMaxDynamicSharedMemorySize, SMEM_BYTES);

    // z-tile slow dim: the 4 a-group blocks of one z-tile are co-resident and
    // share x0/x2 slices in L2.
    dim3 grid(4, ZH / 32);
    einnet_fused5_kernel<<<grid, 256, SMEM_BYTES>>>(x0, x1, x2, out);
}